// round 1
// baseline (speedup 1.0000x reference)
#include <cuda_runtime.h>
#include <cstdint>

// Problem shape (fixed by the dataset problem)
#define B_  32
#define T_  1600
#define C_  1024
#define L_  128
#define S_  257          // 2*L+1
#define ES  132          // padded emission stride (129 used)
#define NEGF (-1e30f)

// Device scratch (allocation-free rule: __device__ globals)
__device__ float g_em[(size_t)B_ * T_ * ES];   // ~27 MB compact emissions
__device__ float g_lse[(size_t)B_ * T_];       // per-(b,t) logsumexp

// ---------------------------------------------------------------------------
// Pass 1: one warp per (b,t) row of log_probs.
//  - logsumexp over C=1024 -> g_lse
//  - gather blank + 128 target-class emissions -> g_em
// ---------------------------------------------------------------------------
__global__ void __launch_bounds__(256) ctc_pass1(
    const float* __restrict__ lp,       // [B,T,C]
    const int*   __restrict__ targets)  // [B,L]
{
    int warp = (blockIdx.x * blockDim.x + threadIdx.x) >> 5;
    int lane = threadIdx.x & 31;
    if (warp >= B_ * T_) return;

    int b = warp / T_;

    const float* row = lp + (size_t)warp * C_;
    const float4* row4 = (const float4*)row;

    // Load 1024 floats: 8 float4 per lane, coalesced.
    float4 v[8];
    float m = NEGF;
#pragma unroll
    for (int k = 0; k < 8; ++k) {
        v[k] = row4[lane + 32 * k];
        m = fmaxf(m, fmaxf(fmaxf(v[k].x, v[k].y), fmaxf(v[k].z, v[k].w)));
    }
#pragma unroll
    for (int o = 16; o; o >>= 1) m = fmaxf(m, __shfl_xor_sync(0xffffffffu, m, o));

    float s = 0.f;
#pragma unroll
    for (int k = 0; k < 8; ++k) {
        s += __expf(v[k].x - m) + __expf(v[k].y - m)
           + __expf(v[k].z - m) + __expf(v[k].w - m);
    }
#pragma unroll
    for (int o = 16; o; o >>= 1) s += __shfl_xor_sync(0xffffffffu, s, o);

    if (lane == 0) g_lse[warp] = m + __logf(s);

    // Gather compact emissions: col 0 = blank(class 0), col 1+j = targets[b][j]
    float* emrow = g_em + (size_t)warp * ES;
    const int* tg = targets + b * L_;
#pragma unroll
    for (int j = lane; j < 129; j += 32) {
        int cls = (j == 0) ? 0 : tg[j - 1];
        emrow[j] = row[cls];   // L1/L2 hit: this row was just streamed
    }
}

// ---------------------------------------------------------------------------
// Pass 2: alpha recursion. One block per batch, 160 threads.
// Thread t owns states s0=2t, s1=2t+1 (t=0..128 active; 257 states; s=257 masked).
// Alpha in SMEM ping-pong with 2 NEG guard cells in front.
// ---------------------------------------------------------------------------
#define PF 4   // emission register-prefetch depth

__global__ void __launch_bounds__(160, 1) ctc_alpha(
    const int* __restrict__ targets,
    const int* __restrict__ in_len,
    const int* __restrict__ tgt_len,
    float*     __restrict__ out)
{
    int b   = blockIdx.x;
    int tid = threadIdx.x;

    __shared__ float buf[2][264];  // [guard -2,-1][states 0..257][pad]
    __shared__ float sred[160];

    int Tin = in_len[b];
    int tl  = tgt_len[b];
    int Sb  = 2 * tl + 1;

    // init ping-pong buffers (incl. guard cells) to NEG
    for (int i = tid; i < 2 * 264; i += 160) ((float*)buf)[i] = NEGF;

    // normalizer: sum of lse over t < Tin (deterministic block reduce)
    const float* lseb = g_lse + (size_t)b * T_;
    float acc = 0.f;
    for (int t = tid; t < Tin; t += 160) acc += lseb[t];
    sred[tid] = acc;
    __syncthreads();

    // per-thread state config
    bool activeT = (tid <= 128);
    int  emcol   = (tid < 128) ? (1 + tid) : 0;
    bool skip1   = false;
    if (tid >= 1 && tid < 128) {
        int tj = targets[b * L_ + tid];
        int tp = targets[b * L_ + tid - 1];
        skip1 = (tj != tp);
    }
    bool v0 = (2 * tid     < Sb);
    bool v1 = (2 * tid + 1 < Sb);

    const float* emb = g_em + (size_t)b * T_ * ES;

    float norm = 0.f;
    if (tid == 0) {
        for (int i = 0; i < 160; ++i) norm += sred[i];
        // t = 0 init: only states 0 and 1 reachable
        buf[0][2 + 0] = emb[0];                 // blank, always valid (Sb>=3)
        buf[0][2 + 1] = emb[1];                 // first label
    }

    // emission prefetch pipeline (global, L2-resident after pass1)
    float pb[PF], pl[PF];
#pragma unroll
    for (int i = 0; i < PF; ++i) {
        int t = 1 + i;
        if (t < Tin) { pb[i] = emb[(size_t)t * ES]; pl[i] = emb[(size_t)t * ES + emcol]; }
        else         { pb[i] = 0.f; pl[i] = 0.f; }
    }
    __syncthreads();

    int p = 0;
    int nsteps = Tin - 1;
    for (int base = 0; base < nsteps; base += PF) {
#pragma unroll
        for (int u = 0; u < PF; ++u) {
            int t = 1 + base + u;          // uniform across block
            if (t < Tin) {
                float eb = pb[u], el = pl[u];
                int tn = t + PF;
                if (tn < Tin) {
                    pb[u] = emb[(size_t)tn * ES];
                    pl[u] = emb[(size_t)tn * ES + emcol];
                }
                if (activeT) {
                    // prev alpha: states s0-2 .. s0+1 at buf[p][2*tid .. 2*tid+3]
                    float a_m2 = buf[p][2 * tid];
                    float a_m1 = buf[p][2 * tid + 1];
                    float a_0  = buf[p][2 * tid + 2];
                    float a_p1 = buf[p][2 * tid + 3];

                    // even state s0: logaddexp(a_0, a_m1)   (skip always false)
                    float m0 = fmaxf(a_0, a_m1);
                    float d0 = fminf(a_0, a_m1) - m0;
                    float n0 = eb + m0 + __logf(1.f + __expf(d0));
                    n0 = v0 ? n0 : NEGF;

                    // odd state s1: logaddexp3(a_p1, a_0, skip ? a_m1 : NEG)
                    float c  = skip1 ? a_m1 : NEGF;
                    float m1 = fmaxf(fmaxf(a_p1, a_0), c);
                    float ss = __expf(a_p1 - m1) + __expf(a_0 - m1) + __expf(c - m1);
                    float n1 = el + m1 + __logf(ss);
                    n1 = v1 ? n1 : NEGF;

                    buf[1 - p][2 * tid + 2] = n0;
                    buf[1 - p][2 * tid + 3] = n1;
                }
            }
            __syncthreads();
            if (t < Tin) p ^= 1;          // uniform
        }
    }

    if (tid == 0) {
        float la = buf[p][2 + Sb - 1];
        float lb = buf[p][2 + Sb - 2];
        float m  = fmaxf(la, lb);
        float llh = m + __logf(__expf(la - m) + __expf(lb - m));
        out[b] = -(llh - norm);
    }
}

// ---------------------------------------------------------------------------
extern "C" void kernel_launch(void* const* d_in, const int* in_sizes, int n_in,
                              void* d_out, int out_size)
{
    const float* lp      = (const float*)d_in[0];
    const int*   targets = (const int*)d_in[1];
    const int*   ilen    = (const int*)d_in[2];
    const int*   tlen    = (const int*)d_in[3];
    float*       out     = (float*)d_out;
    (void)in_sizes; (void)n_in; (void)out_size;

    // Pass 1: 51200 rows, 8 warps/block
    ctc_pass1<<<(B_ * T_) / 8, 256>>>(lp, targets);
    // Pass 2: one block per batch
    ctc_alpha<<<B_, 160>>>(targets, ilen, tlen, out);
}

// round 5
// speedup vs baseline: 1.6937x; 1.6937x over previous
#include <cuda_runtime.h>
#include <cstdint>

// Problem shape (fixed by the dataset problem)
#define B_  32
#define T_  1600
#define C_  1024
#define L_  128
#define SPAD 288          // padded per-state emission stride (257 used)
#define LOG2E 1.44269504088896f

// Device scratch (allocation-free rule: __device__ globals)
__device__ float g_emS[(size_t)B_ * T_ * SPAD];  // 2^(lp*log2e - K) per extended state
__device__ float g_lse[B_ * T_];                 // per-(b,t) logsumexp (normalizer)
__device__ int   g_K[B_ * T_];                   // per-row power-of-2 prescale exponent

// ---------------------------------------------------------------------------
// Pass 1: one warp per (b,t) row of log_probs.
// ---------------------------------------------------------------------------
__global__ void __launch_bounds__(256) ctc_pass1(
    const float* __restrict__ lp,       // [B,T,C]
    const int*   __restrict__ targets)  // [B,L]
{
    int warp = (blockIdx.x * blockDim.x + threadIdx.x) >> 5;
    int lane = threadIdx.x & 31;
    if (warp >= B_ * T_) return;

    int b = warp / T_;

    const float* row = lp + (size_t)warp * C_;
    const float4* row4 = (const float4*)row;

    float4 v[8];
    float m = -1e30f;
#pragma unroll
    for (int k = 0; k < 8; ++k) {
        v[k] = row4[lane + 32 * k];
        m = fmaxf(m, fmaxf(fmaxf(v[k].x, v[k].y), fmaxf(v[k].z, v[k].w)));
    }
#pragma unroll
    for (int o = 16; o; o >>= 1) m = fmaxf(m, __shfl_xor_sync(0xffffffffu, m, o));

    float s = 0.f;
#pragma unroll
    for (int k = 0; k < 8; ++k) {
        s += __expf(v[k].x - m) + __expf(v[k].y - m)
           + __expf(v[k].z - m) + __expf(v[k].w - m);
    }
#pragma unroll
    for (int o = 16; o; o >>= 1) s += __shfl_xor_sync(0xffffffffu, s, o);

    if (lane == 0) g_lse[warp] = m + __logf(s);

    // Gather extended-state log-probs (ext[s]=blank if s even else targets[(s-1)/2])
    const int* tg = targets + b * L_;
    float ev[9];
#pragma unroll
    for (int j = 0; j < 9; ++j) {
        int s2 = lane + 32 * j;
        if (s2 < 257) {
            int cls = (s2 & 1) ? tg[(s2 - 1) >> 1] : 0;
            ev[j] = row[cls];            // L1-hot
        } else ev[j] = -1e30f;
    }
    float rm = ev[0];
#pragma unroll
    for (int j = 1; j < 9; ++j) rm = fmaxf(rm, ev[j]);
#pragma unroll
    for (int o = 16; o; o >>= 1) rm = fmaxf(rm, __shfl_xor_sync(0xffffffffu, rm, o));

    int K = (int)ceilf(rm * LOG2E);      // row max scaled into (0.5, 1]
    if (lane == 0) g_K[warp] = K;

    float* emrow = g_emS + (size_t)warp * SPAD;
    float negK = -(float)K;
#pragma unroll
    for (int j = 0; j < 9; ++j) {
        int s2 = lane + 32 * j;
        if (s2 < 257) emrow[s2] = exp2f(fmaf(ev[j], LOG2E, negK));
    }
}

// ---------------------------------------------------------------------------
// Pass 2: forward recursion in probability space with PER-LANE power-of-2
// scaling and per-step exact rebase on cross-lane injection.
// One WARP per batch. Lane l owns states 8l..8l+7 (a0..a7); lane 31 also
// owns state 256 (a8).
// ---------------------------------------------------------------------------
__global__ void __launch_bounds__(32, 1) ctc_alpha(
    const int* __restrict__ targets,
    const int* __restrict__ in_len,
    const int* __restrict__ tgt_len,
    float*     __restrict__ out)
{
    int b    = blockIdx.x;
    int lane = threadIdx.x;

    int Tin = in_len[b];
    int Sb  = 2 * tgt_len[b] + 1;

    // normalizer (sum of lse) and prescale-exponent sum over t < Tin
    const float* lseb = g_lse + b * T_;
    const int*   Kb   = g_K + b * T_;
    float nacc = 0.f; int kacc = 0;
    for (int t = lane; t < Tin; t += 32) { nacc += lseb[t]; kacc += Kb[t]; }
#pragma unroll
    for (int o = 16; o; o >>= 1) {
        nacc += __shfl_xor_sync(0xffffffffu, nacc, o);
        kacc += __shfl_xor_sync(0xffffffffu, kacc, o);
    }
    float norm = nacc;
    int   Ksum = kacc;

    // skip flags for local odd states (global s = 8*lane + 2j+1, label li = 4*lane+j)
    const int* tg = targets + b * L_;
    float skf0, skf1, skf2, skf3;
    {
        int li0 = 4 * lane;
        skf0 = (li0 >= 1 && tg[li0] != tg[li0 - 1]) ? 1.f : 0.f;
        skf1 = (tg[li0 + 1] != tg[li0]) ? 1.f : 0.f;
        skf2 = (tg[li0 + 2] != tg[li0 + 1]) ? 1.f : 0.f;
        skf3 = (tg[li0 + 3] != tg[li0 + 2]) ? 1.f : 0.f;
    }

    const float* emb = g_emS + (size_t)b * T_ * SPAD;

    // t = 0 init: only states 0 and 1 reachable
    float a0 = 0.f, a1 = 0.f, a2 = 0.f, a3 = 0.f, a4 = 0.f,
          a5 = 0.f, a6 = 0.f, a7 = 0.f, a8 = 0.f;
    if (lane == 0) { a0 = emb[0]; a1 = emb[1]; }
    // per-lane scale: true = local * 2^lsc. Empty lanes anchored very low so
    // the first injection triggers an exact rebase.
    int lsc = (lane == 0) ? 0 : -(1 << 28);

    int nst = Tin - 1;   // steps t = 1..Tin-1

    // emission prefetch ring, depth 8
    float4 rA[8], rB[8]; float rC[8];
#pragma unroll
    for (int i = 0; i < 8; ++i) {
        int t = 1 + i;
        if (t <= nst) {
            const float4* p = (const float4*)(emb + (size_t)t * SPAD + 8 * lane);
            rA[i] = p[0]; rB[i] = p[1];
            rC[i] = emb[(size_t)t * SPAD + 256];
        } else {
            rA[i] = make_float4(0.f, 0.f, 0.f, 0.f); rB[i] = rA[i]; rC[i] = 0.f;
        }
    }

// One recursion step with exact per-step rebase:
//  - a7 sent as (mantissa bits, absolute exponent = biased_exp + lsc)
//  - d = e_in - lsc_recv; if d > 161 the incoming value dominates any lane
//    content (<= 2^10 local) by > 24 bits: rescale lane by 2^-(d-161) exactly
//    (power of two; flush-to-zero only when content is provably invisible),
//    fold into lsc. Then am1 = mant * 2^(d-127) with d in (0,161]; d <= 0 means
//    the injection is > 126 bits below lane max (>= 2^-52 local) -> drop.
#define CTC_STEP(EA, EB, EC)                                                 \
    {                                                                        \
        int abits = __float_as_int(a7);                                      \
        int esend = (abits >> 23) + lsc;                                     \
        if (abits < 0x00800000) esend = -(1 << 30);                          \
        int m_in = __shfl_up_sync(0xffffffffu, abits, 1);                    \
        int e_in = __shfl_up_sync(0xffffffffu, esend, 1);                    \
        int d = e_in - lsc;                                                  \
        int excess = (d > 161) ? (d - 161) : 0;                              \
        lsc += excess;                                                       \
        d -= excess;                                                         \
        int efd = 127 - excess; efd = (efd < 0) ? 0 : efd;                   \
        float down = __int_as_float(efd << 23);                              \
        float am1 = (d > 0 && lane != 0)                                     \
                  ? __int_as_float((m_in & 0x007fffff) | (d << 23)) : 0.f;   \
        float b0 = a0 * down, b1 = a1 * down, b2 = a2 * down,                \
              b3 = a3 * down, b4 = a4 * down, b5 = a5 * down,                \
              b6 = a6 * down, b7 = a7 * down, b8 = a8 * down;                \
        float n0 = (EA).x * (b0 + am1);                                      \
        float n1 = (EA).y * fmaf(skf0, am1, b1 + b0);                        \
        float n2 = (EA).z * (b2 + b1);                                       \
        float n3 = (EA).w * fmaf(skf1, b1, b3 + b2);                         \
        float n4 = (EB).x * (b4 + b3);                                       \
        float n5 = (EB).y * fmaf(skf2, b3, b5 + b4);                         \
        float n6 = (EB).z * (b6 + b5);                                       \
        float n7 = (EB).w * fmaf(skf3, b5, b7 + b6);                         \
        float n8 = (EC)   * (b8 + b7);                                       \
        a0 = n0; a1 = n1; a2 = n2; a3 = n3; a4 = n4;                         \
        a5 = n5; a6 = n6; a7 = n7; a8 = n8;                                  \
    }

// Lane-local renorm: bring lane max back to [1,2), fold exponent into lsc.
// Empty lanes (exp field 0) are untouched.
#define CTC_RENORM()                                                         \
    {                                                                        \
        float lm = fmaxf(fmaxf(fmaxf(a0, a1), fmaxf(a2, a3)),                \
                         fmaxf(fmaxf(a4, a5), fmaxf(a6, a7)));               \
        if (lane == 31) lm = fmaxf(lm, a8);                                  \
        int elm = __float_as_int(lm) >> 23;                                  \
        float sc = (elm == 0) ? 1.0f : __int_as_float((254 - elm) << 23);    \
        lsc += (elm == 0) ? 0 : (elm - 127);                                 \
        a0 *= sc; a1 *= sc; a2 *= sc; a3 *= sc; a4 *= sc;                    \
        a5 *= sc; a6 *= sc; a7 *= sc; a8 *= sc;                              \
    }

    int done = 0;
    while (done + 8 <= nst) {
#pragma unroll
        for (int u = 0; u < 8; ++u) {
            float4 ea = rA[u], eb2 = rB[u]; float ec = rC[u];
            int tn = 1 + done + u + 8;
            if (tn <= nst) {
                const float4* p = (const float4*)(emb + (size_t)tn * SPAD + 8 * lane);
                rA[u] = p[0]; rB[u] = p[1];
                rC[u] = emb[(size_t)tn * SPAD + 256];
            }
            CTC_STEP(ea, eb2, ec);
            if (u == 3 || u == 7) CTC_RENORM();
        }
        done += 8;
    }

    // tail (< 8 steps): direct loads (L2-hot); <=7 steps without renorm is safe
    for (int t = 1 + done; t <= nst; ++t) {
        const float* rowp = emb + (size_t)t * SPAD;
        const float4* p = (const float4*)(rowp + 8 * lane);
        float4 ea = p[0], eb2 = p[1]; float ec = rowp[256];
        CTC_STEP(ea, eb2, ec);
    }

    // final readout: combine states Sb-1, Sb-2 in log space (per-lane scales)
    __shared__ float fin[257];
    __shared__ int   flsc[32];
    fin[8 * lane + 0] = a0; fin[8 * lane + 1] = a1;
    fin[8 * lane + 2] = a2; fin[8 * lane + 3] = a3;
    fin[8 * lane + 4] = a4; fin[8 * lane + 5] = a5;
    fin[8 * lane + 6] = a6; fin[8 * lane + 7] = a7;
    if (lane == 31) fin[256] = a8;
    flsc[lane] = lsc;
    __syncwarp();

    if (lane == 0) {
        int sA = Sb - 1, sB = Sb - 2;
        int lA_ = sA >> 3; if (lA_ > 31) lA_ = 31;
        int lB_ = sB >> 3; if (lB_ > 31) lB_ = 31;
        float  va = fin[sA], vb = fin[sB];
        double lA = (va > 0.f) ? (log2((double)va) + (double)flsc[lA_]) : -1e300;
        double lB = (vb > 0.f) ? (log2((double)vb) + (double)flsc[lB_]) : -1e300;
        double hi = (lA > lB) ? lA : lB;
        double lo = (lA > lB) ? lB : lA;
        double l2sum = hi + log2(1.0 + exp2(lo - hi));
        double llh = 0.6931471805599453 * (l2sum + (double)Ksum);
        out[b] = (float)((double)norm - llh);
    }
#undef CTC_STEP
#undef CTC_RENORM
}

// ---------------------------------------------------------------------------
extern "C" void kernel_launch(void* const* d_in, const int* in_sizes, int n_in,
                              void* d_out, int out_size)
{
    const float* lp      = (const float*)d_in[0];
    const int*   targets = (const int*)d_in[1];
    const int*   ilen    = (const int*)d_in[2];
    const int*   tlen    = (const int*)d_in[3];
    float*       out     = (float*)d_out;
    (void)in_sizes; (void)n_in; (void)out_size;

    ctc_pass1<<<(B_ * T_) / 8, 256>>>(lp, targets);
    ctc_alpha<<<B_, 32>>>(targets, ilen, tlen, out);
}

// round 6
// speedup vs baseline: 2.2715x; 1.3412x over previous
#include <cuda_runtime.h>
#include <cstdint>

// Problem shape (fixed by the dataset problem)
#define B_  32
#define T_  1600
#define C_  1024
#define L_  128
#define LOG2E 1.44269504088896f

// Device scratch (allocation-free rule: __device__ globals).
// g_emOdd: per (b,t) row, 128 odd-extended-state emissions, laid out as one
// float4 per lane (lane l -> states 8l+1,8l+3,8l+5,8l+7). 16 rows of padding
// so the prefetch ring may read past the last row harmlessly.
__device__ float g_emOdd[((size_t)B_ * T_ + 16) * 128];
__device__ float g_bl [B_ * T_ + 16];   // scaled blank emission per row (all even states)
__device__ float g_lse[B_ * T_];        // per-(b,t) logsumexp (normalizer)
__device__ int   g_K  [B_ * T_];        // per-row power-of-2 prescale exponent

// ---------------------------------------------------------------------------
// Pass 1: one warp per (b,t) row of log_probs.
//  - logsumexp over C=1024 -> g_lse
//  - K = ceil(max(ext log-probs) * log2e); blank em + 4 odd ems per lane,
//    each stored as exp2(lp*log2e - K).
// ---------------------------------------------------------------------------
__global__ void __launch_bounds__(256) ctc_pass1(
    const float* __restrict__ lp,       // [B,T,C]
    const int*   __restrict__ targets)  // [B,L]
{
    int warp = (blockIdx.x * blockDim.x + threadIdx.x) >> 5;
    int lane = threadIdx.x & 31;
    if (warp >= B_ * T_) return;

    int b = warp / T_;
    const float* row = lp + (size_t)warp * C_;
    const float4* row4 = (const float4*)row;

    float4 v[8];
    float m = -1e30f;
#pragma unroll
    for (int k = 0; k < 8; ++k) {
        v[k] = row4[lane + 32 * k];
        m = fmaxf(m, fmaxf(fmaxf(v[k].x, v[k].y), fmaxf(v[k].z, v[k].w)));
    }
#pragma unroll
    for (int o = 16; o; o >>= 1) m = fmaxf(m, __shfl_xor_sync(0xffffffffu, m, o));

    float s = 0.f;
#pragma unroll
    for (int k = 0; k < 8; ++k) {
        s += __expf(v[k].x - m) + __expf(v[k].y - m)
           + __expf(v[k].z - m) + __expf(v[k].w - m);
    }
#pragma unroll
    for (int o = 16; o; o >>= 1) s += __shfl_xor_sync(0xffffffffu, s, o);

    if (lane == 0) g_lse[warp] = m + __logf(s);

    // 4 labels per lane -> odd states 8l+1..8l+7 ; blank shared by all even.
    const int4 tgv = *(const int4*)(targets + b * L_ + 4 * lane);
    float e0 = row[tgv.x], e1 = row[tgv.y], e2 = row[tgv.z], e3 = row[tgv.w];
    float blv = row[0];

    float rm = fmaxf(fmaxf(fmaxf(e0, e1), fmaxf(e2, e3)), blv);
#pragma unroll
    for (int o = 16; o; o >>= 1) rm = fmaxf(rm, __shfl_xor_sync(0xffffffffu, rm, o));

    int K = (int)ceilf(rm * LOG2E);     // ext-row max lands in (0.5, 1]
    float nK = -(float)K;

    float4 outv;
    outv.x = exp2f(fmaf(e0, LOG2E, nK));
    outv.y = exp2f(fmaf(e1, LOG2E, nK));
    outv.z = exp2f(fmaf(e2, LOG2E, nK));
    outv.w = exp2f(fmaf(e3, LOG2E, nK));
    *(float4*)(g_emOdd + ((size_t)warp << 7) + (lane << 2)) = outv;

    if (lane == 0) {
        g_K[warp]  = K;
        g_bl[warp] = exp2f(fmaf(blv, LOG2E, nK));
    }
}

// ---------------------------------------------------------------------------
// Pass 2: forward recursion, one WARP per batch, per-lane power-of-2 scaling,
// halo-3 ghost states refreshed every 2 steps (no shfl/scale math inside steps).
// Lane l owns states 8l..8l+7 (o0..o7); lane 31 also state 256 (o8).
// h1,h2,h3 = states 8l-3,8l-2,8l-1 (refreshed from left's o5,o6,o7).
// ---------------------------------------------------------------------------
__global__ void __launch_bounds__(32, 1) ctc_alpha(
    const int* __restrict__ targets,
    const int* __restrict__ in_len,
    const int* __restrict__ tgt_len,
    float*     __restrict__ out)
{
    int b    = blockIdx.x;
    int lane = threadIdx.x;

    int Tin = in_len[b];
    int Sb  = 2 * tgt_len[b] + 1;

    // normalizer (sum of lse) and prescale-exponent sum over t < Tin
    const float* lseb = g_lse + b * T_;
    const int*   Kb   = g_K + b * T_;
    float nacc = 0.f; int kacc = 0;
    for (int t = lane; t < Tin; t += 32) { nacc += lseb[t]; kacc += Kb[t]; }
#pragma unroll
    for (int o = 16; o; o >>= 1) {
        nacc += __shfl_xor_sync(0xffffffffu, nacc, o);
        kacc += __shfl_xor_sync(0xffffffffu, kacc, o);
    }
    float norm = nacc;
    int   Ksum = kacc;

    // skip flags: own odd states (li = 4l..4l+3) + halo state 8l-1 (li = 4l-1)
    const int* tg = targets + b * L_;
    int li = 4 * lane;
    float sk1 = (lane > 0 && tg[li]     != tg[li - 1]) ? 1.f : 0.f;
    float sk3 = (tg[li + 1] != tg[li])     ? 1.f : 0.f;
    float sk5 = (tg[li + 2] != tg[li + 1]) ? 1.f : 0.f;
    float sk7 = (tg[li + 3] != tg[li + 2]) ? 1.f : 0.f;
    float skh = (lane > 0 && tg[li - 1] != tg[li - 2]) ? 1.f : 0.f;

    const size_t rowb = (size_t)b * T_;
    const float4* emO = (const float4*)g_emOdd;    // 32 float4 per row

    float o0=0.f,o1=0.f,o2=0.f,o3=0.f,o4=0.f,o5=0.f,o6=0.f,o7=0.f,o8=0.f;
    float h1=0.f,h2=0.f,h3=0.f;
    int lsc = 0;
    if (lane == 0) { o0 = g_bl[rowb]; o1 = g_emOdd[rowb << 7]; }   // t=0 init

    int nst = Tin - 1;   // steps t = 1..Tin-1 (Tin >= 800 always)

// Exchange + lane-local renorm (every 2 steps). All scale factors exact 2^k.
#define EXCH_RENORM()                                                        \
    {                                                                        \
        float lm = fmaxf(fmaxf(fmaxf(o0,o1),fmaxf(o2,o3)),                   \
                         fmaxf(fmaxf(o4,o5),fmaxf(o6,o7)));                  \
        lm = fmaxf(lm, (lane == 31) ? o8 : 0.f);                             \
        int elm = __float_as_int(lm) >> 23;                                  \
        float vL1 = __shfl_up_sync(0xffffffffu, o5, 1);                      \
        float vL2 = __shfl_up_sync(0xffffffffu, o6, 1);                      \
        float vL3 = __shfl_up_sync(0xffffffffu, o7, 1);                      \
        int  lscL = __shfl_up_sync(0xffffffffu, lsc, 1);                     \
        int  elmL = __shfl_up_sync(0xffffffffu, elm, 1);                     \
        bool isE  = (elm == 0);                                              \
        bool eLok = (elmL != 0) && (lane != 0);                              \
        int sAbsB = lscL + elmL;                                             \
        int myAbs = lsc + elm;                                               \
        int exc   = (eLok && !isE) ? (sAbsB - myAbs - 60) : 0;               \
        exc = (exc > 0) ? exc : 0;                                           \
        int lscR;                                                            \
        if (isE) lscR = eLok ? (sAbsB - 127) : lsc;                          \
        else     lscR = lsc + (elm - 127) + exc;                             \
        int eo = lsc - lscR + 127; eo = ::min(::max(eo, 0), 254);            \
        float sc = __int_as_float(eo << 23);                                 \
        int ef = eLok ? (lscL - lscR + 127) : 0;                             \
        ef = ::min(::max(ef, 0), 254);                                       \
        float ff = __int_as_float(ef << 23);                                 \
        o0*=sc; o1*=sc; o2*=sc; o3*=sc; o4*=sc;                              \
        o5*=sc; o6*=sc; o7*=sc; o8*=sc;                                      \
        h1 = vL1 * ff; h2 = vL2 * ff; h3 = vL3 * ff;                         \
        lsc = lscR;                                                          \
    }

// First step of a pair: also advance halo state 8l-1 (em via shfl of left E.w)
#define STEP_A(E_, BLc)                                                      \
    {                                                                        \
        float hw  = __shfl_up_sync(0xffffffffu, (E_).w, 1);                  \
        float nh3 = hw * fmaf(skh, h1, h3 + h2);                             \
        float n0 = (BLc)  * (o0 + h3);                                       \
        float n1 = (E_).x * fmaf(sk1, h3, o1 + o0);                          \
        float n2 = (BLc)  * (o2 + o1);                                       \
        float n3 = (E_).y * fmaf(sk3, o1, o3 + o2);                          \
        float n4 = (BLc)  * (o4 + o3);                                       \
        float n5 = (E_).z * fmaf(sk5, o3, o5 + o4);                          \
        float n6 = (BLc)  * (o6 + o5);                                       \
        float n7 = (E_).w * fmaf(sk7, o5, o7 + o6);                          \
        float n8 = (BLc)  * (o8 + o7);                                       \
        o0=n0;o1=n1;o2=n2;o3=n3;o4=n4;o5=n5;o6=n6;o7=n7;o8=n8; h3=nh3;       \
    }

#define STEP_B(E_, BLc)                                                      \
    {                                                                        \
        float n0 = (BLc)  * (o0 + h3);                                       \
        float n1 = (E_).x * fmaf(sk1, h3, o1 + o0);                          \
        float n2 = (BLc)  * (o2 + o1);                                       \
        float n3 = (E_).y * fmaf(sk3, o1, o3 + o2);                          \
        float n4 = (BLc)  * (o4 + o3);                                       \
        float n5 = (E_).z * fmaf(sk5, o3, o5 + o4);                          \
        float n6 = (BLc)  * (o6 + o5);                                       \
        float n7 = (E_).w * fmaf(sk7, o5, o7 + o6);                          \
        float n8 = (BLc)  * (o8 + o7);                                       \
        o0=n0;o1=n1;o2=n2;o3=n3;o4=n4;o5=n5;o6=n6;o7=n7;o8=n8;               \
    }

    // prefetch ring, depth 10 (rows t = 1..10); pad rows make OOB reads safe
    float4 E[10]; float BL[10];
#pragma unroll
    for (int i = 0; i < 10; ++i) {
        E[i]  = emO[(rowb + 1 + i) * 32 + lane];
        BL[i] = g_bl[rowb + 1 + i];
    }

    const float4* pE  = emO + (rowb + 11) * 32 + lane;   // prefetch target row
    const float*  pBL = g_bl + rowb + 11;

    int k = 0;
    while (k + 10 <= nst) {
#pragma unroll
        for (int u = 0; u < 5; ++u) {
            EXCH_RENORM();
            {   // step k + 2u  (slot 2u)
                float4 Ec = E[2*u]; float blc = BL[2*u];
                E[2*u]  = pE[(2*u) * 32];
                BL[2*u] = pBL[2*u];
                STEP_A(Ec, blc);
            }
            {   // step k + 2u + 1  (slot 2u+1)
                float4 Ec = E[2*u+1]; float blc = BL[2*u+1];
                E[2*u+1]  = pE[(2*u+1) * 32];
                BL[2*u+1] = pBL[2*u+1];
                STEP_B(Ec, blc);
            }
        }
        k += 10;
        pE += 320;
        pBL += 10;
    }

    // tail (< 10 steps): direct L2-hot loads
    while (k < nst) {
        EXCH_RENORM();
        {
            float4 Ec = emO[(rowb + 1 + k) * 32 + lane];
            float blc = g_bl[rowb + 1 + k];
            STEP_A(Ec, blc); ++k;
        }
        if (k < nst) {
            float4 Ec = emO[(rowb + 1 + k) * 32 + lane];
            float blc = g_bl[rowb + 1 + k];
            STEP_B(Ec, blc); ++k;
        }
    }

    // final readout: combine states Sb-1, Sb-2 in log space (per-lane scales)
    __shared__ float fin[257];
    __shared__ int   flsc[32];
    fin[8*lane+0]=o0; fin[8*lane+1]=o1; fin[8*lane+2]=o2; fin[8*lane+3]=o3;
    fin[8*lane+4]=o4; fin[8*lane+5]=o5; fin[8*lane+6]=o6; fin[8*lane+7]=o7;
    if (lane == 31) fin[256] = o8;
    flsc[lane] = lsc;
    __syncwarp();

    if (lane == 0) {
        int sA = Sb - 1, sB = Sb - 2;
        int lA_ = sA >> 3; if (lA_ > 31) lA_ = 31;
        int lB_ = sB >> 3; if (lB_ > 31) lB_ = 31;
        float  va = fin[sA], vb = fin[sB];
        double lA = (va > 0.f) ? (log2((double)va) + (double)flsc[lA_]) : -1e300;
        double lB = (vb > 0.f) ? (log2((double)vb) + (double)flsc[lB_]) : -1e300;
        double hi = (lA > lB) ? lA : lB;
        double lo = (lA > lB) ? lB : lA;
        double l2sum = hi + log2(1.0 + exp2(lo - hi));
        double llh = 0.6931471805599453 * (l2sum + (double)Ksum);
        out[b] = (float)((double)norm - llh);
    }
#undef EXCH_RENORM
#undef STEP_A
#undef STEP_B
}

// ---------------------------------------------------------------------------
extern "C" void kernel_launch(void* const* d_in, const int* in_sizes, int n_in,
                              void* d_out, int out_size)
{
    const float* lp      = (const float*)d_in[0];
    const int*   targets = (const int*)d_in[1];
    const int*   ilen    = (const int*)d_in[2];
    const int*   tlen    = (const int*)d_in[3];
    float*       out     = (float*)d_out;
    (void)in_sizes; (void)n_in; (void)out_size;

    ctc_pass1<<<(B_ * T_) / 8, 256>>>(lp, targets);
    ctc_alpha<<<B_, 32>>>(targets, ilen, tlen, out);
}

// round 8
// speedup vs baseline: 2.3783x; 1.0471x over previous
#include <cuda_runtime.h>
#include <cstdint>

// Problem shape (fixed by the dataset problem)
#define B_  32
#define T_  1600
#define C_  1024
#define L_  128

// Device scratch (allocation-free rule: __device__ globals).
// g_emOdd: per (b,t) row, 128 odd-state emission RATIOS r = p(label)/p(blank),
// one float4 per lane (lane l -> states 8l+1,8l+3,8l+5,8l+7).
// 16 pad rows so the prefetch ring may read past the end harmlessly.
__device__ float g_emOdd[((size_t)B_ * T_ + 16) * 128];
__device__ float g_bll[B_ * T_];        // log-prob of blank per row (nats)
__device__ float g_lse[B_ * T_];        // per-(b,t) logsumexp (normalizer)

// ---------------------------------------------------------------------------
// Pass 1: one warp per (b,t) row of log_probs.
//  - logsumexp over C=1024 -> g_lse
//  - blank log-prob -> g_bll ; odd-state ratios exp(lp_label - lp_blank) -> g_emOdd
// ---------------------------------------------------------------------------
__global__ void __launch_bounds__(256) ctc_pass1(
    const float* __restrict__ lp,       // [B,T,C]
    const int*   __restrict__ targets)  // [B,L]
{
    int warp = (blockIdx.x * blockDim.x + threadIdx.x) >> 5;
    int lane = threadIdx.x & 31;
    if (warp >= B_ * T_) return;

    int b = warp / T_;
    const float* row = lp + (size_t)warp * C_;
    const float4* row4 = (const float4*)row;

    float4 v[8];
    float m = -1e30f;
#pragma unroll
    for (int k = 0; k < 8; ++k) {
        v[k] = row4[lane + 32 * k];
        m = fmaxf(m, fmaxf(fmaxf(v[k].x, v[k].y), fmaxf(v[k].z, v[k].w)));
    }
#pragma unroll
    for (int o = 16; o; o >>= 1) m = fmaxf(m, __shfl_xor_sync(0xffffffffu, m, o));

    float s = 0.f;
#pragma unroll
    for (int k = 0; k < 8; ++k) {
        s += __expf(v[k].x - m) + __expf(v[k].y - m)
           + __expf(v[k].z - m) + __expf(v[k].w - m);
    }
#pragma unroll
    for (int o = 16; o; o >>= 1) s += __shfl_xor_sync(0xffffffffu, s, o);

    if (lane == 0) g_lse[warp] = m + __logf(s);

    // 4 labels per lane -> odd states 8l+1..8l+7 ; ratios vs blank.
    const int4 tgv = *(const int4*)(targets + b * L_ + 4 * lane);
    float blv = row[0];
    float4 outv;
    outv.x = __expf(row[tgv.x] - blv);
    outv.y = __expf(row[tgv.y] - blv);
    outv.z = __expf(row[tgv.z] - blv);
    outv.w = __expf(row[tgv.w] - blv);
    *(float4*)(g_emOdd + ((size_t)warp << 7) + (lane << 2)) = outv;

    if (lane == 0) g_bll[warp] = blv;
}

// ---------------------------------------------------------------------------
// Pass 2: blank-factored forward recursion, one WARP per batch.
// beta recursion: even states  b' = b + b_left   (pure FADD)
//                 odd states   b' = r * (b + b_left + sk * b_left2)
// alpha = beta * prod(blank_t); log correction added at the end.
// Lane l owns states 8l..8l+7 (o0..o7); o8 is state 8l+8 (real only on
// lane 31 = state 256; elsewhere a harmless shadow). Per-lane power-of-2
// scale lsc, renormalized every 4 steps; cross-lane term each step:
// h3 = shfl_up(o7) * ff with ff = 2^(lscL - lsc) fixed within a period
// (ff = 0 on lane 0).
// ---------------------------------------------------------------------------
__global__ void __launch_bounds__(32, 1) ctc_alpha(
    const int* __restrict__ targets,
    const int* __restrict__ in_len,
    const int* __restrict__ tgt_len,
    float*     __restrict__ out)
{
    int b    = blockIdx.x;
    int lane = threadIdx.x;

    int Tin = in_len[b];
    int Sb  = 2 * tgt_len[b] + 1;

    const size_t rowb = (size_t)b * T_;

    // prologue reductions: norm = sum lse; blsum = sum_{t>=1} lp_blank
    const float* lseb = g_lse + rowb;
    const float* bllb = g_bll + rowb;
    float nacc = 0.f, bacc = 0.f;
    for (int t = lane; t < Tin; t += 32) { nacc += lseb[t]; bacc += bllb[t]; }
#pragma unroll
    for (int o = 16; o; o >>= 1) {
        nacc += __shfl_xor_sync(0xffffffffu, nacc, o);
        bacc += __shfl_xor_sync(0xffffffffu, bacc, o);
    }
    float norm  = nacc;
    float blsum = bacc - bllb[0];   // exclude t = 0

    // skip flags for own odd states (label index li = 4*lane + j)
    const int* tg = targets + b * L_;
    int li = 4 * lane;
    float sk1 = (lane > 0 && tg[li] != tg[li - 1]) ? 1.f : 0.f;
    float sk3 = (tg[li + 1] != tg[li])     ? 1.f : 0.f;
    float sk5 = (tg[li + 2] != tg[li + 1]) ? 1.f : 0.f;
    float sk7 = (tg[li + 3] != tg[li + 2]) ? 1.f : 0.f;

    const float4* emO = (const float4*)g_emOdd;    // 32 float4 per row

    // t = 0 init: beta_0 = alpha_0 (no blank factor yet):
    // state0 = p0(blank), state1 = p0(label0) = r * p0(blank)
    float o0=0.f,o1=0.f,o2=0.f,o3=0.f,o4=0.f,o5=0.f,o6=0.f,o7=0.f,o8=0.f;
    if (lane == 0) {
        float eb0 = __expf(bllb[0]);
        o0 = eb0;
        o1 = g_emOdd[rowb << 7] * eb0;
    }
    int   lsc = 0;
    float ff  = 0.f;

    int nst = Tin - 1;   // steps t = 1..Tin-1 (Tin >= 800)

// Renorm boundary (every 4 steps): rebase per-lane scale so the lane-pair max
// lands in [1,2) (biased exp 127). All scale factors exact powers of 2.
#define BOUNDARY()                                                           \
    {                                                                        \
        float lm = fmaxf(fmaxf(fmaxf(o0,o1),fmaxf(o2,o3)),                   \
                         fmaxf(fmaxf(o4,o5),fmaxf(fmaxf(o6,o7),o8)));        \
        int elm   = __float_as_int(lm) >> 23;                                \
        int myabs = lsc + elm;                                               \
        int absL  = __shfl_up_sync(0xffffffffu, myabs, 1);                   \
        int lscN  = ::max(myabs, absL) - 127;                                \
        int eo = ::min(::max(lsc - lscN + 127, 0), 254);                     \
        float sc = __int_as_float(eo << 23);                                 \
        int lscLN = __shfl_up_sync(0xffffffffu, lscN, 1);                    \
        int ef = ::min(::max(lscLN - lscN + 127, 0), 254);                   \
        ff = (lane == 0) ? 0.f : __int_as_float(ef << 23);                   \
        o0*=sc; o1*=sc; o2*=sc; o3*=sc; o4*=sc;                              \
        o5*=sc; o6*=sc; o7*=sc; o8*=sc;                                      \
        lsc = lscN;                                                          \
    }

// One time step (blank factored out): 17 fma-pipe ops + 1 shfl.
#define STEP(Ec)                                                             \
    {                                                                        \
        float h3 = __shfl_up_sync(0xffffffffu, o7, 1) * ff;                  \
        float n0 = o0 + h3;                                                  \
        float n1 = (Ec).x * fmaf(sk1, h3, o1 + o0);                          \
        float n2 = o2 + o1;                                                  \
        float n3 = (Ec).y * fmaf(sk3, o1, o3 + o2);                          \
        float n4 = o4 + o3;                                                  \
        float n5 = (Ec).z * fmaf(sk5, o3, o5 + o4);                          \
        float n6 = o6 + o5;                                                  \
        float n7 = (Ec).w * fmaf(sk7, o5, o7 + o6);                          \
        float n8 = o8 + o7;                                                  \
        o0=n0;o1=n1;o2=n2;o3=n3;o4=n4;o5=n5;o6=n6;o7=n7;o8=n8;               \
    }

    // prefetch ring, depth 8 (rows t = 1..8); pad rows make OOB reads safe
    float4 E[8];
#pragma unroll
    for (int i = 0; i < 8; ++i) E[i] = emO[(rowb + 1 + i) * 32 + lane];

    const float4* pE = emO + (rowb + 9) * 32 + lane;   // next prefetch row

    int k = 0;
    while (k + 8 <= nst) {
        BOUNDARY();
#pragma unroll
        for (int u = 0; u < 4; ++u) {
            float4 Ec = E[u]; E[u] = pE[u * 32]; STEP(Ec);
        }
        BOUNDARY();
#pragma unroll
        for (int u = 4; u < 8; ++u) {
            float4 Ec = E[u]; E[u] = pE[u * 32]; STEP(Ec);
        }
        k += 8;
        pE += 256;
    }

    // tail (< 8 steps): one boundary, direct L2-hot loads (growth bounded)
    BOUNDARY();
    while (k < nst) {
        float4 Ec = emO[(rowb + 1 + k) * 32 + lane];
        STEP(Ec);
        ++k;
    }

    // final readout: combine states Sb-1, Sb-2 in log space (per-lane scales)
    __shared__ float fin[257];
    __shared__ int   flsc[32];
    fin[8*lane+0]=o0; fin[8*lane+1]=o1; fin[8*lane+2]=o2; fin[8*lane+3]=o3;
    fin[8*lane+4]=o4; fin[8*lane+5]=o5; fin[8*lane+6]=o6; fin[8*lane+7]=o7;
    if (lane == 31) fin[256] = o8;
    flsc[lane] = lsc;
    __syncwarp();

    if (lane == 0) {
        int sA = Sb - 1, sB = Sb - 2;
        int lA_ = sA >> 3; if (lA_ > 31) lA_ = 31;
        int lB_ = sB >> 3; if (lB_ > 31) lB_ = 31;
        float  va = fin[sA], vb = fin[sB];
        double lA = (va > 0.f) ? (log2((double)va) + (double)flsc[lA_]) : -1e300;
        double lB = (vb > 0.f) ? (log2((double)vb) + (double)flsc[lB_]) : -1e300;
        double hi = (lA > lB) ? lA : lB;
        double lo = (lA > lB) ? lB : lA;
        double l2sum = hi + log2(1.0 + exp2(lo - hi));
        double llh = 0.6931471805599453 * l2sum + (double)blsum;
        out[b] = (float)((double)norm - llh);
    }
#undef BOUNDARY
#undef STEP
}

// ---------------------------------------------------------------------------
extern "C" void kernel_launch(void* const* d_in, const int* in_sizes, int n_in,
                              void* d_out, int out_size)
{
    const float* lp      = (const float*)d_in[0];
    const int*   targets = (const int*)d_in[1];
    const int*   ilen    = (const int*)d_in[2];
    const int*   tlen    = (const int*)d_in[3];
    float*       out     = (float*)d_out;
    (void)in_sizes; (void)n_in; (void)out_size;

    ctc_pass1<<<(B_ * T_) / 8, 256>>>(lp, targets);
    ctc_alpha<<<B_, 32>>>(targets, ilen, tlen, out);
}

// round 10
// speedup vs baseline: 3.5454x; 1.4907x over previous
#include <cuda_runtime.h>
#include <cstdint>

// Problem shape (fixed by the dataset problem)
#define B_  32
#define T_  1600
#define C_  1024
#define L_  128

// Device scratch (allocation-free rule: __device__ globals).
// g_emOdd: per (b,t) row, 128 odd-state emission RATIOS r = p(label)/p(blank),
// one float4 per lane (lane l -> states 8l+1,8l+3,8l+5,8l+7).
// 64 pad rows so ring refill and L2 prefetch may run past the end harmlessly.
__device__ float g_emOdd[((size_t)B_ * T_ + 64) * 128];
__device__ float g_bll[B_ * T_];        // log-prob of blank per row (nats)
__device__ float g_lse[B_ * T_];        // per-(b,t) logsumexp (normalizer)

// ---------------------------------------------------------------------------
// Pass 1: one warp per (b,t) row of log_probs.
// ---------------------------------------------------------------------------
__global__ void __launch_bounds__(256) ctc_pass1(
    const float* __restrict__ lp,       // [B,T,C]
    const int*   __restrict__ targets)  // [B,L]
{
    int warp = (blockIdx.x * blockDim.x + threadIdx.x) >> 5;
    int lane = threadIdx.x & 31;
    if (warp >= B_ * T_) return;

    int b = warp / T_;
    const float* row = lp + (size_t)warp * C_;
    const float4* row4 = (const float4*)row;

    float4 v[8];
    float m = -1e30f;
#pragma unroll
    for (int k = 0; k < 8; ++k) {
        v[k] = row4[lane + 32 * k];
        m = fmaxf(m, fmaxf(fmaxf(v[k].x, v[k].y), fmaxf(v[k].z, v[k].w)));
    }
#pragma unroll
    for (int o = 16; o; o >>= 1) m = fmaxf(m, __shfl_xor_sync(0xffffffffu, m, o));

    float s = 0.f;
#pragma unroll
    for (int k = 0; k < 8; ++k) {
        s += __expf(v[k].x - m) + __expf(v[k].y - m)
           + __expf(v[k].z - m) + __expf(v[k].w - m);
    }
#pragma unroll
    for (int o = 16; o; o >>= 1) s += __shfl_xor_sync(0xffffffffu, s, o);

    if (lane == 0) g_lse[warp] = m + __logf(s);

    // 4 labels per lane -> odd states 8l+1..8l+7 ; ratios vs blank.
    const int4 tgv = *(const int4*)(targets + b * L_ + 4 * lane);
    float blv = row[0];
    float4 outv;
    outv.x = __expf(row[tgv.x] - blv);
    outv.y = __expf(row[tgv.y] - blv);
    outv.z = __expf(row[tgv.z] - blv);
    outv.w = __expf(row[tgv.w] - blv);
    *(float4*)(g_emOdd + ((size_t)warp << 7) + (lane << 2)) = outv;

    if (lane == 0) g_bll[warp] = blv;
}

// ---------------------------------------------------------------------------
// Pass 2: blank-factored forward recursion, one WARP per batch.
// Even states: b' = b + b_left (FADD). Odd: b' = r*(b + b_left + sk*b_left2).
// alpha = beta * prod(blank_t); correction folded into prologue sums.
// Per-lane power-of-2 scale lsc, renorm every 4 steps, lane-pair max anchored
// to [1,2) (R8-proven numerics). Cross-lane term each step:
// h3 = shfl_up(o7) * ff, ff constant within a period (0 on lane 0).
// Emission ring: 16 rows in registers + prefetch.global.L2 48 rows ahead.
// ---------------------------------------------------------------------------
__global__ void __launch_bounds__(32, 1) ctc_alpha(
    const int* __restrict__ targets,
    const int* __restrict__ in_len,
    const int* __restrict__ tgt_len,
    float*     __restrict__ out)
{
    int b    = blockIdx.x;
    int lane = threadIdx.x;

    int Tin = in_len[b];
    int Sb  = 2 * tgt_len[b] + 1;

    const size_t rowb = (size_t)b * T_;

    // prologue reductions: norm = sum lse; blsum = sum_{t>=1} lp_blank
    const float* lseb = g_lse + rowb;
    const float* bllb = g_bll + rowb;
    float nacc = 0.f, bacc = 0.f;
    for (int t = lane; t < Tin; t += 32) { nacc += lseb[t]; bacc += bllb[t]; }
#pragma unroll
    for (int o = 16; o; o >>= 1) {
        nacc += __shfl_xor_sync(0xffffffffu, nacc, o);
        bacc += __shfl_xor_sync(0xffffffffu, bacc, o);
    }
    float norm  = nacc;
    float blsum = bacc - bllb[0];   // exclude t = 0

    // skip flags for own odd states (label index li = 4*lane + j)
    const int* tg = targets + b * L_;
    int li = 4 * lane;
    float sk1 = (lane > 0 && tg[li] != tg[li - 1]) ? 1.f : 0.f;
    float sk3 = (tg[li + 1] != tg[li])     ? 1.f : 0.f;
    float sk5 = (tg[li + 2] != tg[li + 1]) ? 1.f : 0.f;
    float sk7 = (tg[li + 3] != tg[li + 2]) ? 1.f : 0.f;

    const float4* emO = (const float4*)g_emOdd;    // 32 float4 per row

    // t = 0 init
    float o0=0.f,o1=0.f,o2=0.f,o3=0.f,o4=0.f,o5=0.f,o6=0.f,o7=0.f,o8=0.f;
    if (lane == 0) {
        float eb0 = __expf(bllb[0]);
        o0 = eb0;
        o1 = g_emOdd[rowb << 7] * eb0;
    }
    int   lsc = 0;
    float ff  = 0.f;

    int nst = Tin - 1;   // steps t = 1..Tin-1 (Tin >= 800)

// Renorm boundary (every 4 steps): anchor lane-pair max in [1,2) (biased 127,
// exactly R8's proven numerics). The left lane's new scale is recomputed
// locally from absL/absLL (provably identical to shfl of its lscN) so the two
// shfls are independent. All scale factors exact powers of 2.
#define BOUNDARY()                                                           \
    {                                                                        \
        float lm = fmaxf(fmaxf(fmaxf(o0,o1),fmaxf(o2,o3)),                   \
                         fmaxf(fmaxf(o4,o5),fmaxf(fmaxf(o6,o7),o8)));        \
        int elm   = __float_as_int(lm) >> 23;                                \
        int myabs = lsc + elm;                                               \
        int absL  = __shfl_up_sync(0xffffffffu, myabs, 1);                   \
        int absLL = __shfl_up_sync(0xffffffffu, myabs, 2);                   \
        if (lane < 1) absL  = myabs;                                         \
        if (lane < 2) absLL = -(1 << 29);                                    \
        int lscN  = ::max(myabs, absL)  - 127;                               \
        int lscNL = ::max(absL,  absLL) - 127;                               \
        int eo = ::min(::max(lsc - lscN + 127, 0), 254);                     \
        float sc = __int_as_float(eo << 23);                                 \
        int ef = ::min(::max(lscNL - lscN + 127, 0), 254);                   \
        ff = (lane == 0) ? 0.f : __int_as_float(ef << 23);                   \
        o0*=sc; o1*=sc; o2*=sc; o3*=sc; o4*=sc;                              \
        o5*=sc; o6*=sc; o7*=sc; o8*=sc;                                      \
        lsc = lscN;                                                          \
    }

// One time step: 17 fma-pipe ops + 1 shfl.
#define STEP(Ec)                                                             \
    {                                                                        \
        float h3 = __shfl_up_sync(0xffffffffu, o7, 1) * ff;                  \
        float n0 = o0 + h3;                                                  \
        float n1 = (Ec).x * fmaf(sk1, h3, o1 + o0);                          \
        float n2 = o2 + o1;                                                  \
        float n3 = (Ec).y * fmaf(sk3, o1, o3 + o2);                          \
        float n4 = o4 + o3;                                                  \
        float n5 = (Ec).z * fmaf(sk5, o3, o5 + o4);                          \
        float n6 = o6 + o5;                                                  \
        float n7 = (Ec).w * fmaf(sk7, o5, o7 + o6);                          \
        float n8 = o8 + o7;                                                  \
        o0=n0;o1=n1;o2=n2;o3=n3;o4=n4;o5=n5;o6=n6;o7=n7;o8=n8;               \
    }

    // emission ring, depth 16 (rows t = 1..16); pad rows make OOB reads safe
    float4 E[16];
#pragma unroll
    for (int i = 0; i < 16; ++i) E[i] = emO[(rowb + 1 + i) * 32 + lane];

    const float4* pE = emO + (rowb + 17) * 32 + lane;   // refill base (row 1+k+16)

    int k = 0;
    while (k + 16 <= nst) {
#pragma unroll
        for (int q = 0; q < 4; ++q) {
            BOUNDARY();
#pragma unroll
            for (int j = 0; j < 4; ++j) {
                int u = 4 * q + j;
                float4 Ec = E[u];
                E[u] = pE[u * 32];                          // refill row 1+k+u+16
                asm volatile("prefetch.global.L2 [%0];"
                             :: "l"(pE + (u + 32) * 32));   // row 1+k+u+48 -> L2
                STEP(Ec);
            }
        }
        k  += 16;
        pE += 512;
    }

    // tail: <=4 steps per boundary, direct L2-hot loads
    while (k < nst) {
        BOUNDARY();
#pragma unroll 1
        for (int j = 0; j < 4 && k < nst; ++j, ++k) {
            float4 Ec = emO[(rowb + 1 + k) * 32 + lane];
            STEP(Ec);
        }
    }

    // final readout: combine states Sb-1, Sb-2 in log space (per-lane scales)
    __shared__ float fin[257];
    __shared__ int   flsc[32];
    fin[8*lane+0]=o0; fin[8*lane+1]=o1; fin[8*lane+2]=o2; fin[8*lane+3]=o3;
    fin[8*lane+4]=o4; fin[8*lane+5]=o5; fin[8*lane+6]=o6; fin[8*lane+7]=o7;
    if (lane == 31) fin[256] = o8;
    flsc[lane] = lsc;
    __syncwarp();

    if (lane == 0) {
        int sA = Sb - 1, sB = Sb - 2;
        int lA_ = sA >> 3; if (lA_ > 31) lA_ = 31;
        int lB_ = sB >> 3; if (lB_ > 31) lB_ = 31;
        float  va = fin[sA], vb = fin[sB];
        double lA = (va > 0.f) ? (log2((double)va) + (double)flsc[lA_]) : -1e300;
        double lB = (vb > 0.f) ? (log2((double)vb) + (double)flsc[lB_]) : -1e300;
        double hi = (lA > lB) ? lA : lB;
        double lo = (lA > lB) ? lB : lA;
        double l2sum = hi + log2(1.0 + exp2(lo - hi));
        double llh = 0.6931471805599453 * l2sum + (double)blsum;
        out[b] = (float)((double)norm - llh);
    }
#undef BOUNDARY
#undef STEP
}

// ---------------------------------------------------------------------------
extern "C" void kernel_launch(void* const* d_in, const int* in_sizes, int n_in,
                              void* d_out, int out_size)
{
    const float* lp      = (const float*)d_in[0];
    const int*   targets = (const int*)d_in[1];
    const int*   ilen    = (const int*)d_in[2];
    const int*   tlen    = (const int*)d_in[3];
    float*       out     = (float*)d_out;
    (void)in_sizes; (void)n_in; (void)out_size;

    ctc_pass1<<<(B_ * T_) / 8, 256>>>(lp, targets);
    ctc_alpha<<<B_, 32>>>(targets, ilen, tlen, out);
}